// round 2
// baseline (speedup 1.0000x reference)
#include <cuda_runtime.h>
#include <math.h>

#define NNODE 20000
#define DIM 256
#define HEADS 4
#define NE 100000
#define HC 1024   // HEADS * C, C == DIM

// ---------------- scratch (device globals; no allocation allowed) ----------
__device__ __align__(16) float g_dinv[NNODE];
__device__ __align__(16) float g_h[NNODE * DIM];       // f_all @ W_gcn
__device__ __align__(16) float g_x[NNODE * DIM];       // GCN out -> later reused for tf
__device__ __align__(16) float g_q[NNODE * HC];
__device__ __align__(16) float g_k[NNODE * HC];
__device__ __align__(16) float g_v[NNODE * HC];
__device__ __align__(16) float g_skip[NNODE * DIM];
__device__ __align__(16) float g_logits[NE * HEADS];   // logits -> exp values
__device__ __align__(16) float g_m[NNODE * HEADS];
__device__ __align__(16) float g_denom[NNODE * HEADS];
__device__ __align__(16) float g_agg[NNODE * DIM];     // head-averaged attention output

// CSR by destination node
__device__ int g_cnt[NNODE];
__device__ int g_rowptr[NNODE + 1];
__device__ int g_fill[NNODE];
__device__ int g_eid[NE];

// ---------------- init -----------------------------------------------------
__global__ void k_init() {
    int i = blockIdx.x * blockDim.x + threadIdx.x;
    if (i < NNODE) g_cnt[i] = 0;
    if (i < NNODE * HEADS) g_denom[i] = 0.0f;
}

__global__ void k_count(const int* __restrict__ dst) {
    int e = blockIdx.x * blockDim.x + threadIdx.x;
    if (e < NE) atomicAdd(&g_cnt[dst[e]], 1);
}

// single-block scan (1024 threads, Hillis-Steele per 1024-chunk)
__global__ void k_scan() {
    __shared__ int sh[1024];
    __shared__ int soff;
    int tid = threadIdx.x;
    if (tid == 0) soff = 0;
    __syncthreads();
    for (int base = 0; base < NNODE; base += 1024) {
        int i = base + tid;
        int v = (i < NNODE) ? g_cnt[i] : 0;
        sh[tid] = v;
        __syncthreads();
        for (int d = 1; d < 1024; d <<= 1) {
            int t = (tid >= d) ? sh[tid - d] : 0;
            __syncthreads();
            sh[tid] += t;
            __syncthreads();
        }
        if (i < NNODE) {
            int excl = soff + sh[tid] - v;
            g_rowptr[i] = excl;
            g_fill[i]   = excl;
        }
        __syncthreads();
        if (tid == 1023) soff += sh[1023];
        __syncthreads();
    }
    if (tid == 0) g_rowptr[NNODE] = NE;
}

__global__ void k_dinv() {
    int i = blockIdx.x * blockDim.x + threadIdx.x;
    if (i < NNODE) {
        float d = (float)(g_rowptr[i + 1] - g_rowptr[i]) + 1.0f;  // + self loop
        g_dinv[i] = rsqrtf(d);
    }
}

__global__ void k_fill(const int* __restrict__ dst) {
    int e = blockIdx.x * blockDim.x + threadIdx.x;
    if (e < NE) {
        int pos = atomicAdd(&g_fill[dst[e]], 1);
        g_eid[pos] = e;
    }
}

// ---------------- SGEMM (128x128, 8x8 microtile, double-buffered) ----------
// C[M,N] = A[M,K] @ op(B) (+bias, relu).  BTRANS=false: B is [K,N] row-major.
// BTRANS=true: B is [N,K] row-major.  bias_mode: 0 none, 1 per-col, 2 per-row.
template <bool BTRANS>
__global__ __launch_bounds__(256, 2) void sgemm(
    const float* __restrict__ A, const float* __restrict__ B,
    const float* __restrict__ bias, float* __restrict__ C,
    int M, int N, int K, int bias_mode, int do_relu)
{
    const int BM = 128, BN = 128, BK = 16;
    __shared__ float As[2][BK][BM + 4];
    __shared__ float Bs[2][BK][BN + 4];

    int tid = threadIdx.x;
    int brow = blockIdx.y * BM;
    int bcol = blockIdx.x * BN;

    float4 pa[2], pb[2];

    // ---- tile load helpers (to registers) ----
    auto loadA = [&](int k0) {
#pragma unroll
        for (int t = 0; t < 2; t++) {
            int idx = tid * 2 + t;
            int r = idx >> 2, c = (idx & 3) * 4;
            if (brow + r < M)
                pa[t] = *(const float4*)&A[(size_t)(brow + r) * K + k0 + c];
            else
                pa[t] = make_float4(0.f, 0.f, 0.f, 0.f);
        }
    };
    auto loadB = [&](int k0) {
#pragma unroll
        for (int t = 0; t < 2; t++) {
            int idx = tid * 2 + t;
            if (!BTRANS) {
                int kr = idx >> 5, c = (idx & 31) * 4;
                if (bcol + c < N)
                    pb[t] = *(const float4*)&B[(size_t)(k0 + kr) * N + bcol + c];
                else
                    pb[t] = make_float4(0.f, 0.f, 0.f, 0.f);
            } else {
                int r = idx >> 2, c = (idx & 3) * 4;
                if (bcol + r < N)
                    pb[t] = *(const float4*)&B[(size_t)(bcol + r) * K + k0 + c];
                else
                    pb[t] = make_float4(0.f, 0.f, 0.f, 0.f);
            }
        }
    };
    auto storeTiles = [&](int buf) {
#pragma unroll
        for (int t = 0; t < 2; t++) {
            int idx = tid * 2 + t;
            int r = idx >> 2, c = (idx & 3) * 4;
            As[buf][c + 0][r] = pa[t].x; As[buf][c + 1][r] = pa[t].y;
            As[buf][c + 2][r] = pa[t].z; As[buf][c + 3][r] = pa[t].w;
            if (!BTRANS) {
                int kr = idx >> 5, cc = (idx & 31) * 4;
                Bs[buf][kr][cc + 0] = pb[t].x; Bs[buf][kr][cc + 1] = pb[t].y;
                Bs[buf][kr][cc + 2] = pb[t].z; Bs[buf][kr][cc + 3] = pb[t].w;
            } else {
                Bs[buf][c + 0][r] = pb[t].x; Bs[buf][c + 1][r] = pb[t].y;
                Bs[buf][c + 2][r] = pb[t].z; Bs[buf][c + 3][r] = pb[t].w;
            }
        }
    };

    float acc[8][8];
#pragma unroll
    for (int i = 0; i < 8; i++)
#pragma unroll
        for (int j = 0; j < 8; j++) acc[i][j] = 0.0f;

    int ty = tid >> 4;   // 0..15
    int tx = tid & 15;   // 0..15

    loadA(0); loadB(0);
    storeTiles(0);
    __syncthreads();

    int nk = K / BK;
    for (int kt = 0; kt < nk; kt++) {
        int cur = kt & 1, nxt = cur ^ 1;
        if (kt + 1 < nk) { loadA((kt + 1) * BK); loadB((kt + 1) * BK); }

#pragma unroll
        for (int kk = 0; kk < BK; kk++) {
            float4 a0 = *(const float4*)&As[cur][kk][ty * 8];
            float4 a1 = *(const float4*)&As[cur][kk][ty * 8 + 4];
            float4 b0 = *(const float4*)&Bs[cur][kk][tx * 8];
            float4 b1 = *(const float4*)&Bs[cur][kk][tx * 8 + 4];
            float a[8] = {a0.x, a0.y, a0.z, a0.w, a1.x, a1.y, a1.z, a1.w};
            float b[8] = {b0.x, b0.y, b0.z, b0.w, b1.x, b1.y, b1.z, b1.w};
#pragma unroll
            for (int i = 0; i < 8; i++)
#pragma unroll
                for (int j = 0; j < 8; j++)
                    acc[i][j] = fmaf(a[i], b[j], acc[i][j]);
        }
        if (kt + 1 < nk) {
            storeTiles(nxt);
            __syncthreads();
        }
    }

#pragma unroll
    for (int i = 0; i < 8; i++) {
        int row = brow + ty * 8 + i;
        if (row >= M) continue;
#pragma unroll
        for (int j = 0; j < 8; j++) {
            int col = bcol + tx * 8 + j;
            if (col >= N) continue;
            float v = acc[i][j];
            if (bias_mode == 1) v += bias[col];
            else if (bias_mode == 2) v += bias[row];
            if (do_relu) v = fmaxf(v, 0.0f);
            C[(size_t)row * N + col] = v;
        }
    }
}

// ---------------- GCN aggregation: warp per destination node ----------------
__global__ void k_gcn_node(const int* __restrict__ src, const float* __restrict__ b_gcn) {
    int wid  = (blockIdx.x * blockDim.x + threadIdx.x) >> 5;
    int lane = threadIdx.x & 31;
    if (wid >= NNODE) return;
    int start = g_rowptr[wid], end = g_rowptr[wid + 1];
    float dn = g_dinv[wid];
    int c = lane * 8;
    float4 acc0 = make_float4(0.f, 0.f, 0.f, 0.f);
    float4 acc1 = make_float4(0.f, 0.f, 0.f, 0.f);
    for (int idx = start; idx < end; idx++) {
        int e = g_eid[idx];
        int s = src[e];
        float w = g_dinv[s] * dn;
        const float* hp = &g_h[(size_t)s * DIM + c];
        float4 h0 = *(const float4*)hp;
        float4 h1 = *(const float4*)(hp + 4);
        acc0.x = fmaf(w, h0.x, acc0.x); acc0.y = fmaf(w, h0.y, acc0.y);
        acc0.z = fmaf(w, h0.z, acc0.z); acc0.w = fmaf(w, h0.w, acc0.w);
        acc1.x = fmaf(w, h1.x, acc1.x); acc1.y = fmaf(w, h1.y, acc1.y);
        acc1.z = fmaf(w, h1.z, acc1.z); acc1.w = fmaf(w, h1.w, acc1.w);
    }
    // self loop
    float ws = dn * dn;
    const float* hp = &g_h[(size_t)wid * DIM + c];
    float4 h0 = *(const float4*)hp;
    float4 h1 = *(const float4*)(hp + 4);
    float4 bb0 = *(const float4*)&b_gcn[c];
    float4 bb1 = *(const float4*)&b_gcn[c + 4];
    acc0.x = fmaxf(fmaf(ws, h0.x, acc0.x) + bb0.x, 0.f);
    acc0.y = fmaxf(fmaf(ws, h0.y, acc0.y) + bb0.y, 0.f);
    acc0.z = fmaxf(fmaf(ws, h0.z, acc0.z) + bb0.z, 0.f);
    acc0.w = fmaxf(fmaf(ws, h0.w, acc0.w) + bb0.w, 0.f);
    acc1.x = fmaxf(fmaf(ws, h1.x, acc1.x) + bb1.x, 0.f);
    acc1.y = fmaxf(fmaf(ws, h1.y, acc1.y) + bb1.y, 0.f);
    acc1.z = fmaxf(fmaf(ws, h1.z, acc1.z) + bb1.z, 0.f);
    acc1.w = fmaxf(fmaf(ws, h1.w, acc1.w) + bb1.w, 0.f);
    float* o = &g_x[(size_t)wid * DIM + c];
    *(float4*)o = acc0;
    *(float4*)(o + 4) = acc1;
}

// ---------------- attention: logits + per-node max (warp per node-head) -----
__global__ void k_logits_csr(const int* __restrict__ src) {
    int wid  = (blockIdx.x * blockDim.x + threadIdx.x) >> 5;
    int lane = threadIdx.x & 31;
    if (wid >= NNODE * HEADS) return;
    int n = wid >> 2, h = wid & 3;
    int start = g_rowptr[n], end = g_rowptr[n + 1];
    int c = lane * 8;
    const float* qp = &g_q[(size_t)n * HC + h * DIM + c];
    float4 q0 = *(const float4*)qp;
    float4 q1 = *(const float4*)(qp + 4);
    float maxl = -INFINITY;
    for (int idx = start; idx < end; idx++) {
        int e = g_eid[idx];
        int s = src[e];
        const float* kp = &g_k[(size_t)s * HC + h * DIM + c];
        float4 k0 = *(const float4*)kp;
        float4 k1 = *(const float4*)(kp + 4);
        float sum = q0.x * k0.x + q0.y * k0.y + q0.z * k0.z + q0.w * k0.w
                  + q1.x * k1.x + q1.y * k1.y + q1.z * k1.z + q1.w * k1.w;
#pragma unroll
        for (int off = 16; off > 0; off >>= 1)
            sum += __shfl_xor_sync(0xFFFFFFFFu, sum, off);
        float l = sum * (1.0f / 16.0f);   // /sqrt(256)
        if (lane == 0) g_logits[e * HEADS + h] = l;
        maxl = fmaxf(maxl, l);
    }
    if (lane == 0) g_m[n * HEADS + h] = maxl;
}

__global__ void k_expsum(const int* __restrict__ dst) {
    int i = blockIdx.x * blockDim.x + threadIdx.x;
    if (i < NE * HEADS) {
        int e = i >> 2, h = i & 3;
        int d = dst[e];
        float t = __expf(g_logits[i] - g_m[d * HEADS + h]);
        g_logits[i] = t;
        atomicAdd(&g_denom[d * HEADS + h], t);
    }
}

// ---------------- attention aggregation: warp per destination node ----------
__global__ void k_agg_csr(const int* __restrict__ src) {
    int wid  = (blockIdx.x * blockDim.x + threadIdx.x) >> 5;
    int lane = threadIdx.x & 31;
    if (wid >= NNODE) return;
    int start = g_rowptr[wid], end = g_rowptr[wid + 1];
    // 0.25/denom per head (broadcast loads)
    float4 dn = *(const float4*)&g_denom[wid * HEADS];
    float rd0 = 0.25f / fmaxf(dn.x, 1e-16f);
    float rd1 = 0.25f / fmaxf(dn.y, 1e-16f);
    float rd2 = 0.25f / fmaxf(dn.z, 1e-16f);
    float rd3 = 0.25f / fmaxf(dn.w, 1e-16f);
    int c = lane * 8;
    float4 acc0 = make_float4(0.f, 0.f, 0.f, 0.f);
    float4 acc1 = make_float4(0.f, 0.f, 0.f, 0.f);
    for (int idx = start; idx < end; idx++) {
        int e = g_eid[idx];
        int s = src[e];
        float4 t4 = *(const float4*)&g_logits[e * HEADS];  // broadcast
        float a0 = t4.x * rd0, a1 = t4.y * rd1, a2 = t4.z * rd2, a3 = t4.w * rd3;
        const float* vp = &g_v[(size_t)s * HC + c];
#pragma unroll
        for (int h = 0; h < HEADS; h++) {
            float a = (h == 0) ? a0 : (h == 1) ? a1 : (h == 2) ? a2 : a3;
            float4 v0 = *(const float4*)(vp + h * DIM);
            float4 v1 = *(const float4*)(vp + h * DIM + 4);
            acc0.x = fmaf(a, v0.x, acc0.x); acc0.y = fmaf(a, v0.y, acc0.y);
            acc0.z = fmaf(a, v0.z, acc0.z); acc0.w = fmaf(a, v0.w, acc0.w);
            acc1.x = fmaf(a, v1.x, acc1.x); acc1.y = fmaf(a, v1.y, acc1.y);
            acc1.z = fmaf(a, v1.z, acc1.z); acc1.w = fmaf(a, v1.w, acc1.w);
        }
    }
    float* o = &g_agg[(size_t)wid * DIM + c];
    *(float4*)o = acc0;
    *(float4*)(o + 4) = acc1;
}

// ---------------- beta gate -> tf (writes into g_x) -------------------------
__global__ void k_beta(const float* __restrict__ W_beta) {
    int wid  = (blockIdx.x * blockDim.x + threadIdx.x) >> 5;
    int lane = threadIdx.x & 31;
    if (wid >= NNODE) return;
    float o[8], r[8];
    float s = 0.0f;
#pragma unroll
    for (int i = 0; i < 8; i++) {
        int c = lane + i * 32;
        o[i] = g_agg[(size_t)wid * DIM + c];
        r[i] = g_skip[(size_t)wid * DIM + c];
        s += o[i] * W_beta[c] + r[i] * W_beta[DIM + c] + (o[i] - r[i]) * W_beta[2 * DIM + c];
    }
#pragma unroll
    for (int off = 16; off > 0; off >>= 1)
        s += __shfl_xor_sync(0xFFFFFFFFu, s, off);
    float beta = 1.0f / (1.0f + __expf(-s));
#pragma unroll
    for (int i = 0; i < 8; i++) {
        int c = lane + i * 32;
        float tf = beta * r[i] + (1.0f - beta) * o[i];
        g_x[(size_t)wid * DIM + c] = fmaxf(tf, 0.0f);
    }
}

// ---------------- launch ----------------------------------------------------
extern "C" void kernel_launch(void* const* d_in, const int* in_sizes, int n_in,
                              void* d_out, int out_size) {
    const float* f_all  = (const float*)d_in[0];
    const int*   eidx   = (const int*)d_in[1];
    const float* W_gcn  = (const float*)d_in[2];
    const float* b_gcn  = (const float*)d_in[3];
    const float* W_q    = (const float*)d_in[4];
    const float* b_q    = (const float*)d_in[5];
    const float* W_k    = (const float*)d_in[6];
    const float* b_k    = (const float*)d_in[7];
    const float* W_v    = (const float*)d_in[8];
    const float* b_v    = (const float*)d_in[9];
    const float* W_skip = (const float*)d_in[10];
    const float* b_skip = (const float*)d_in[11];
    const float* W_beta = (const float*)d_in[12];
    const float* W_cnn  = (const float*)d_in[13];
    const float* b_cnn  = (const float*)d_in[14];
    float* out = (float*)d_out;

    const int* src = eidx;
    const int* dst = eidx + NE;

    float* d_h    = nullptr; cudaGetSymbolAddress((void**)&d_h,    g_h);
    float* d_x    = nullptr; cudaGetSymbolAddress((void**)&d_x,    g_x);
    float* d_q    = nullptr; cudaGetSymbolAddress((void**)&d_q,    g_q);
    float* d_k    = nullptr; cudaGetSymbolAddress((void**)&d_k,    g_k);
    float* d_v    = nullptr; cudaGetSymbolAddress((void**)&d_v,    g_v);
    float* d_skip = nullptr; cudaGetSymbolAddress((void**)&d_skip, g_skip);

    // CSR build + normalization constants
    k_init<<<(NNODE * HEADS + 255) / 256, 256>>>();
    k_count<<<(NE + 255) / 256, 256>>>(dst);
    k_scan<<<1, 1024>>>();
    k_dinv<<<(NNODE + 255) / 256, 256>>>();
    k_fill<<<(NE + 255) / 256, 256>>>(dst);

    // GCN: h = f_all @ W_gcn, then per-node aggregation
    {
        dim3 grid((DIM + 127) / 128, (NNODE + 127) / 128);
        sgemm<false><<<grid, 256>>>(f_all, W_gcn, nullptr, d_h, NNODE, DIM, DIM, 0, 0);
    }
    k_gcn_node<<<(NNODE * 32 + 255) / 256, 256>>>(src, b_gcn);

    // QKV + skip projections
    {
        dim3 gq((HC + 127) / 128, (NNODE + 127) / 128);
        sgemm<false><<<gq, 256>>>(d_x, W_q, b_q, d_q, NNODE, HC, DIM, 1, 0);
        sgemm<false><<<gq, 256>>>(d_x, W_k, b_k, d_k, NNODE, HC, DIM, 1, 0);
        sgemm<false><<<gq, 256>>>(d_x, W_v, b_v, d_v, NNODE, HC, DIM, 1, 0);
        dim3 gs((DIM + 127) / 128, (NNODE + 127) / 128);
        sgemm<false><<<gs, 256>>>(d_x, W_skip, b_skip, d_skip, NNODE, DIM, DIM, 1, 0);
    }

    // attention
    k_logits_csr<<<(NNODE * HEADS * 32 + 255) / 256, 256>>>(src);
    k_expsum<<<(NE * HEADS + 255) / 256, 256>>>(dst);
    k_agg_csr<<<(NNODE * 32 + 255) / 256, 256>>>(src);

    // gate
    k_beta<<<(NNODE * 32 + 255) / 256, 256>>>(W_beta);

    // final: out[c, n] = sum_d W_cnn[c,d] * tf[n,d] + b_cnn[c]   (NT gemm, per-row bias)
    {
        dim3 grid((NNODE + 127) / 128, (DIM + 127) / 128);
        sgemm<true><<<grid, 256>>>(W_cnn, d_x, b_cnn, out, DIM, NNODE, DIM, 2, 0);
    }
}

// round 3
// speedup vs baseline: 2.2124x; 2.2124x over previous
#include <cuda_runtime.h>
#include <math.h>

#define NNODE 20000
#define DIM 256
#define HEADS 4
#define NE 100000
#define HC 1024   // HEADS * C, C == DIM

// ---------------- scratch (device globals; no allocation allowed) ----------
__device__ __align__(16) float g_dinv[NNODE];
__device__ __align__(16) float g_h[NNODE * DIM];       // f_all @ W_gcn
__device__ __align__(16) float g_x[NNODE * DIM];       // GCN out -> later reused for tf
__device__ __align__(16) float g_q[NNODE * HC];
__device__ __align__(16) float g_k[NNODE * HC];
__device__ __align__(16) float g_v[NNODE * HC];
__device__ __align__(16) float g_skip[NNODE * DIM];
__device__ __align__(16) float g_logits[NE * HEADS];   // logits -> exp values
__device__ __align__(16) float g_denom[NNODE * HEADS];
__device__ __align__(16) float g_agg[NNODE * DIM];     // head-averaged attention output

// CSR by destination node
__device__ int g_cnt[NNODE];
__device__ int g_rowptr[NNODE + 1];
__device__ int g_fill[NNODE];
__device__ int g_eid[NE];

__device__ __forceinline__ unsigned f2tf(float f) {
    unsigned r;
    asm("cvt.rna.tf32.f32 %0, %1;" : "=r"(r) : "f"(f));
    return r;
}

// ---------------- init / CSR build -----------------------------------------
__global__ void k_init() {
    int i = blockIdx.x * blockDim.x + threadIdx.x;
    if (i < NNODE) g_cnt[i] = 0;
}

__global__ void k_count(const int* __restrict__ dst) {
    int e = blockIdx.x * blockDim.x + threadIdx.x;
    if (e < NE) atomicAdd(&g_cnt[dst[e]], 1);
}

__global__ void k_scan() {
    __shared__ int sh[1024];
    __shared__ int soff;
    int tid = threadIdx.x;
    if (tid == 0) soff = 0;
    __syncthreads();
    for (int base = 0; base < NNODE; base += 1024) {
        int i = base + tid;
        int v = (i < NNODE) ? g_cnt[i] : 0;
        sh[tid] = v;
        __syncthreads();
        for (int d = 1; d < 1024; d <<= 1) {
            int t = (tid >= d) ? sh[tid - d] : 0;
            __syncthreads();
            sh[tid] += t;
            __syncthreads();
        }
        if (i < NNODE) {
            int excl = soff + sh[tid] - v;
            g_rowptr[i] = excl;
            g_fill[i]   = excl;
        }
        __syncthreads();
        if (tid == 1023) soff += sh[1023];
        __syncthreads();
    }
    if (tid == 0) g_rowptr[NNODE] = NE;
}

__global__ void k_dinv() {
    int i = blockIdx.x * blockDim.x + threadIdx.x;
    if (i < NNODE) {
        float d = (float)(g_rowptr[i + 1] - g_rowptr[i]) + 1.0f;  // + self loop
        g_dinv[i] = rsqrtf(d);
    }
}

__global__ void k_fill(const int* __restrict__ dst) {
    int e = blockIdx.x * blockDim.x + threadIdx.x;
    if (e < NE) {
        int pos = atomicAdd(&g_fill[dst[e]], 1);
        g_eid[pos] = e;
    }
}

// ---------------- TF32 tensor-core GEMM ------------------------------------
// C[M,N] = A[M,K] @ op(B) (+bias, relu).  BTRANS=false: B is [K,N] row-major.
// BTRANS=true: B is [N,K] row-major.  bias_mode: 0 none, 1 per-col, 2 per-row.
// Block 128x128, BK=16, 8 warps in 2x4 grid, warp tile 64x32 (4x4 m16n8k8).
template <bool BTRANS>
__global__ __launch_bounds__(256) void gemm_tf32(
    const float* __restrict__ A, const float* __restrict__ B,
    const float* __restrict__ bias, float* __restrict__ C,
    int M, int N, int K, int bias_mode, int do_relu)
{
    const int BM = 128, BN = 128, BK = 16, LDSH = 136;
    __shared__ unsigned As[2][BK][LDSH];
    __shared__ unsigned Bs[2][BK][LDSH];

    int tid  = threadIdx.x;
    int wid  = tid >> 5, lane = tid & 31;
    int g = lane >> 2, t = lane & 3;
    int wm = (wid >> 2) * 64;   // 0 or 64
    int wn = (wid & 3) * 32;    // 0,32,64,96
    int brow = blockIdx.y * BM;
    int bcol = blockIdx.x * BN;

    float4 ra[2], rb[2];

    auto loadA = [&](int k0) {
#pragma unroll
        for (int i = 0; i < 2; i++) {
            int id = tid + 256 * i;          // 0..511
            int r = id >> 2, c4 = (id & 3) * 4;
            if (brow + r < M)
                ra[i] = *(const float4*)&A[(size_t)(brow + r) * K + k0 + c4];
            else
                ra[i] = make_float4(0.f, 0.f, 0.f, 0.f);
        }
    };
    auto loadB = [&](int k0) {
#pragma unroll
        for (int i = 0; i < 2; i++) {
            int id = tid + 256 * i;
            if (!BTRANS) {
                int kr = id >> 5, c4 = (id & 31) * 4;
                if (bcol + c4 < N)
                    rb[i] = *(const float4*)&B[(size_t)(k0 + kr) * N + bcol + c4];
                else
                    rb[i] = make_float4(0.f, 0.f, 0.f, 0.f);
            } else {
                int n = id >> 2, c4 = (id & 3) * 4;
                if (bcol + n < N)
                    rb[i] = *(const float4*)&B[(size_t)(bcol + n) * K + k0 + c4];
                else
                    rb[i] = make_float4(0.f, 0.f, 0.f, 0.f);
            }
        }
    };
    auto stTiles = [&](int buf) {
#pragma unroll
        for (int i = 0; i < 2; i++) {
            int id = tid + 256 * i;
            int r = id >> 2, c4 = (id & 3) * 4;
            As[buf][c4 + 0][r] = f2tf(ra[i].x);
            As[buf][c4 + 1][r] = f2tf(ra[i].y);
            As[buf][c4 + 2][r] = f2tf(ra[i].z);
            As[buf][c4 + 3][r] = f2tf(ra[i].w);
            if (!BTRANS) {
                int kr = id >> 5, cc = (id & 31) * 4;
                Bs[buf][kr][cc + 0] = f2tf(rb[i].x);
                Bs[buf][kr][cc + 1] = f2tf(rb[i].y);
                Bs[buf][kr][cc + 2] = f2tf(rb[i].z);
                Bs[buf][kr][cc + 3] = f2tf(rb[i].w);
            } else {
                Bs[buf][c4 + 0][r] = f2tf(rb[i].x);
                Bs[buf][c4 + 1][r] = f2tf(rb[i].y);
                Bs[buf][c4 + 2][r] = f2tf(rb[i].z);
                Bs[buf][c4 + 3][r] = f2tf(rb[i].w);
            }
        }
    };

    float acc[4][4][4];
#pragma unroll
    for (int a = 0; a < 4; a++)
#pragma unroll
        for (int b = 0; b < 4; b++)
#pragma unroll
            for (int c = 0; c < 4; c++) acc[a][b][c] = 0.0f;

    loadA(0); loadB(0);
    stTiles(0);
    __syncthreads();

    int nk = K / BK;
    for (int kt = 0; kt < nk; kt++) {
        int cur = kt & 1, nxt = cur ^ 1;
        if (kt + 1 < nk) { loadA((kt + 1) * BK); loadB((kt + 1) * BK); }

#pragma unroll
        for (int ks = 0; ks < 2; ks++) {
            int k0 = ks * 8;
            unsigned af[4][4], bf[4][2];
#pragma unroll
            for (int mt = 0; mt < 4; mt++) {
                int m = wm + mt * 16;
                af[mt][0] = As[cur][k0 + t][m + g];
                af[mt][1] = As[cur][k0 + t][m + g + 8];
                af[mt][2] = As[cur][k0 + t + 4][m + g];
                af[mt][3] = As[cur][k0 + t + 4][m + g + 8];
            }
#pragma unroll
            for (int nt = 0; nt < 4; nt++) {
                int n = wn + nt * 8;
                bf[nt][0] = Bs[cur][k0 + t][n + g];
                bf[nt][1] = Bs[cur][k0 + t + 4][n + g];
            }
#pragma unroll
            for (int mt = 0; mt < 4; mt++)
#pragma unroll
                for (int nt = 0; nt < 4; nt++)
                    asm volatile(
                        "mma.sync.aligned.m16n8k8.row.col.f32.tf32.tf32.f32 "
                        "{%0,%1,%2,%3}, {%4,%5,%6,%7}, {%8,%9}, {%0,%1,%2,%3};"
                        : "+f"(acc[mt][nt][0]), "+f"(acc[mt][nt][1]),
                          "+f"(acc[mt][nt][2]), "+f"(acc[mt][nt][3])
                        : "r"(af[mt][0]), "r"(af[mt][1]), "r"(af[mt][2]), "r"(af[mt][3]),
                          "r"(bf[nt][0]), "r"(bf[nt][1]));
        }
        if (kt + 1 < nk) {
            __syncthreads();
            stTiles(nxt);
            __syncthreads();
        }
    }

    // epilogue: c0,c1 at (row, 2t),(row, 2t+1); c2,c3 at row+8
#pragma unroll
    for (int mt = 0; mt < 4; mt++) {
#pragma unroll
        for (int nt = 0; nt < 4; nt++) {
            int row = brow + wm + mt * 16 + g;
            int col = bcol + wn + nt * 8 + 2 * t;
            float b0 = 0.f, b1 = 0.f;
            if (bias_mode == 1) { b0 = bias[col]; b1 = bias[col + 1]; }
#pragma unroll
            for (int half = 0; half < 2; half++) {
                int r = row + half * 8;
                if (r >= M || col >= N) continue;
                float v0 = acc[mt][nt][half * 2 + 0];
                float v1 = acc[mt][nt][half * 2 + 1];
                if (bias_mode == 1) { v0 += b0; v1 += b1; }
                else if (bias_mode == 2) { float br = bias[r]; v0 += br; v1 += br; }
                if (do_relu) { v0 = fmaxf(v0, 0.f); v1 = fmaxf(v1, 0.f); }
                *(float2*)&C[(size_t)r * N + col] = make_float2(v0, v1);
            }
        }
    }
}

// ---------------- GCN aggregation: warp per destination node ----------------
__global__ void k_gcn_node(const int* __restrict__ src, const float* __restrict__ b_gcn) {
    int wid  = (blockIdx.x * blockDim.x + threadIdx.x) >> 5;
    int lane = threadIdx.x & 31;
    if (wid >= NNODE) return;
    int start = g_rowptr[wid], end = g_rowptr[wid + 1];
    float dn = g_dinv[wid];
    int c = lane * 8;
    float4 acc0 = make_float4(0.f, 0.f, 0.f, 0.f);
    float4 acc1 = make_float4(0.f, 0.f, 0.f, 0.f);
    for (int idx = start; idx < end; idx++) {
        int e = g_eid[idx];
        int s = src[e];
        float w = g_dinv[s] * dn;
        const float* hp = &g_h[(size_t)s * DIM + c];
        float4 h0 = *(const float4*)hp;
        float4 h1 = *(const float4*)(hp + 4);
        acc0.x = fmaf(w, h0.x, acc0.x); acc0.y = fmaf(w, h0.y, acc0.y);
        acc0.z = fmaf(w, h0.z, acc0.z); acc0.w = fmaf(w, h0.w, acc0.w);
        acc1.x = fmaf(w, h1.x, acc1.x); acc1.y = fmaf(w, h1.y, acc1.y);
        acc1.z = fmaf(w, h1.z, acc1.z); acc1.w = fmaf(w, h1.w, acc1.w);
    }
    float ws = dn * dn;
    const float* hp = &g_h[(size_t)wid * DIM + c];
    float4 h0 = *(const float4*)hp;
    float4 h1 = *(const float4*)(hp + 4);
    float4 bb0 = *(const float4*)&b_gcn[c];
    float4 bb1 = *(const float4*)&b_gcn[c + 4];
    acc0.x = fmaxf(fmaf(ws, h0.x, acc0.x) + bb0.x, 0.f);
    acc0.y = fmaxf(fmaf(ws, h0.y, acc0.y) + bb0.y, 0.f);
    acc0.z = fmaxf(fmaf(ws, h0.z, acc0.z) + bb0.z, 0.f);
    acc0.w = fmaxf(fmaf(ws, h0.w, acc0.w) + bb0.w, 0.f);
    acc1.x = fmaxf(fmaf(ws, h1.x, acc1.x) + bb1.x, 0.f);
    acc1.y = fmaxf(fmaf(ws, h1.y, acc1.y) + bb1.y, 0.f);
    acc1.z = fmaxf(fmaf(ws, h1.z, acc1.z) + bb1.z, 0.f);
    acc1.w = fmaxf(fmaf(ws, h1.w, acc1.w) + bb1.w, 0.f);
    float* o = &g_x[(size_t)wid * DIM + c];
    *(float4*)o = acc0;
    *(float4*)(o + 4) = acc1;
}

// ---------------- attention: logits + softmax (warp per node-head) ----------
__global__ void k_logits_csr(const int* __restrict__ src) {
    int wid  = (blockIdx.x * blockDim.x + threadIdx.x) >> 5;
    int lane = threadIdx.x & 31;
    if (wid >= NNODE * HEADS) return;
    int n = wid >> 2, h = wid & 3;
    int start = g_rowptr[n], end = g_rowptr[n + 1];
    int c = lane * 8;
    const float* qp = &g_q[(size_t)n * HC + h * DIM + c];
    float4 q0 = *(const float4*)qp;
    float4 q1 = *(const float4*)(qp + 4);
    float maxl = -INFINITY;
    // pass 1: raw logits; owner lane (idx-start)&31 stores (so pass 2 reads own write)
    for (int idx = start; idx < end; idx++) {
        int e = g_eid[idx];
        int s = src[e];
        const float* kp = &g_k[(size_t)s * HC + h * DIM + c];
        float4 k0 = *(const float4*)kp;
        float4 k1 = *(const float4*)(kp + 4);
        float sum = q0.x * k0.x + q0.y * k0.y + q0.z * k0.z + q0.w * k0.w
                  + q1.x * k1.x + q1.y * k1.y + q1.z * k1.z + q1.w * k1.w;
#pragma unroll
        for (int off = 16; off > 0; off >>= 1)
            sum += __shfl_xor_sync(0xFFFFFFFFu, sum, off);
        float l = sum * (1.0f / 16.0f);   // /sqrt(256)
        if (lane == ((idx - start) & 31)) g_logits[e * HEADS + h] = l;
        maxl = fmaxf(maxl, l);
    }
    // pass 2: exp + denom (each lane touches only entries it wrote)
    float dsum = 0.0f;
    for (int idx = start + lane; idx < end; idx += 32) {
        int e = g_eid[idx];
        float tv = __expf(g_logits[e * HEADS + h] - maxl);
        g_logits[e * HEADS + h] = tv;
        dsum += tv;
    }
#pragma unroll
    for (int off = 16; off > 0; off >>= 1)
        dsum += __shfl_xor_sync(0xFFFFFFFFu, dsum, off);
    if (lane == 0) g_denom[n * HEADS + h] = dsum;
}

// ---------------- attention aggregation: warp per destination node ----------
__global__ void k_agg_csr(const int* __restrict__ src) {
    int wid  = (blockIdx.x * blockDim.x + threadIdx.x) >> 5;
    int lane = threadIdx.x & 31;
    if (wid >= NNODE) return;
    int start = g_rowptr[wid], end = g_rowptr[wid + 1];
    float4 dn = *(const float4*)&g_denom[wid * HEADS];
    float rd0 = 0.25f / fmaxf(dn.x, 1e-16f);
    float rd1 = 0.25f / fmaxf(dn.y, 1e-16f);
    float rd2 = 0.25f / fmaxf(dn.z, 1e-16f);
    float rd3 = 0.25f / fmaxf(dn.w, 1e-16f);
    int c = lane * 8;
    float4 acc0 = make_float4(0.f, 0.f, 0.f, 0.f);
    float4 acc1 = make_float4(0.f, 0.f, 0.f, 0.f);
    for (int idx = start; idx < end; idx++) {
        int e = g_eid[idx];
        int s = src[e];
        float4 t4 = *(const float4*)&g_logits[e * HEADS];
        float a0 = t4.x * rd0, a1 = t4.y * rd1, a2 = t4.z * rd2, a3 = t4.w * rd3;
        const float* vp = &g_v[(size_t)s * HC + c];
#pragma unroll
        for (int h = 0; h < HEADS; h++) {
            float a = (h == 0) ? a0 : (h == 1) ? a1 : (h == 2) ? a2 : a3;
            float4 v0 = *(const float4*)(vp + h * DIM);
            float4 v1 = *(const float4*)(vp + h * DIM + 4);
            acc0.x = fmaf(a, v0.x, acc0.x); acc0.y = fmaf(a, v0.y, acc0.y);
            acc0.z = fmaf(a, v0.z, acc0.z); acc0.w = fmaf(a, v0.w, acc0.w);
            acc1.x = fmaf(a, v1.x, acc1.x); acc1.y = fmaf(a, v1.y, acc1.y);
            acc1.z = fmaf(a, v1.z, acc1.z); acc1.w = fmaf(a, v1.w, acc1.w);
        }
    }
    float* o = &g_agg[(size_t)wid * DIM + c];
    *(float4*)o = acc0;
    *(float4*)(o + 4) = acc1;
}

// ---------------- beta gate -> tf (writes into g_x) -------------------------
__global__ void k_beta(const float* __restrict__ W_beta) {
    int wid  = (blockIdx.x * blockDim.x + threadIdx.x) >> 5;
    int lane = threadIdx.x & 31;
    if (wid >= NNODE) return;
    float o[8], r[8];
    float s = 0.0f;
#pragma unroll
    for (int i = 0; i < 8; i++) {
        int c = lane + i * 32;
        o[i] = g_agg[(size_t)wid * DIM + c];
        r[i] = g_skip[(size_t)wid * DIM + c];
        s += o[i] * W_beta[c] + r[i] * W_beta[DIM + c] + (o[i] - r[i]) * W_beta[2 * DIM + c];
    }
#pragma unroll
    for (int off = 16; off > 0; off >>= 1)
        s += __shfl_xor_sync(0xFFFFFFFFu, s, off);
    float beta = 1.0f / (1.0f + __expf(-s));
#pragma unroll
    for (int i = 0; i < 8; i++) {
        int c = lane + i * 32;
        float tf = beta * r[i] + (1.0f - beta) * o[i];
        g_x[(size_t)wid * DIM + c] = fmaxf(tf, 0.0f);
    }
}

// ---------------- launch ----------------------------------------------------
extern "C" void kernel_launch(void* const* d_in, const int* in_sizes, int n_in,
                              void* d_out, int out_size) {
    const float* f_all  = (const float*)d_in[0];
    const int*   eidx   = (const int*)d_in[1];
    const float* W_gcn  = (const float*)d_in[2];
    const float* b_gcn  = (const float*)d_in[3];
    const float* W_q    = (const float*)d_in[4];
    const float* b_q    = (const float*)d_in[5];
    const float* W_k    = (const float*)d_in[6];
    const float* b_k    = (const float*)d_in[7];
    const float* W_v    = (const float*)d_in[8];
    const float* b_v    = (const float*)d_in[9];
    const float* W_skip = (const float*)d_in[10];
    const float* b_skip = (const float*)d_in[11];
    const float* W_beta = (const float*)d_in[12];
    const float* W_cnn  = (const float*)d_in[13];
    const float* b_cnn  = (const float*)d_in[14];
    float* out = (float*)d_out;

    const int* src = eidx;
    const int* dst = eidx + NE;

    float* d_h    = nullptr; cudaGetSymbolAddress((void**)&d_h,    g_h);
    float* d_x    = nullptr; cudaGetSymbolAddress((void**)&d_x,    g_x);
    float* d_q    = nullptr; cudaGetSymbolAddress((void**)&d_q,    g_q);
    float* d_k    = nullptr; cudaGetSymbolAddress((void**)&d_k,    g_k);
    float* d_v    = nullptr; cudaGetSymbolAddress((void**)&d_v,    g_v);
    float* d_skip = nullptr; cudaGetSymbolAddress((void**)&d_skip, g_skip);

    // CSR build + normalization constants
    k_init<<<(NNODE + 255) / 256, 256>>>();
    k_count<<<(NE + 255) / 256, 256>>>(dst);
    k_scan<<<1, 1024>>>();
    k_dinv<<<(NNODE + 255) / 256, 256>>>();
    k_fill<<<(NE + 255) / 256, 256>>>(dst);

    // GCN: h = f_all @ W_gcn, then per-node aggregation
    {
        dim3 grid((DIM + 127) / 128, (NNODE + 127) / 128);
        gemm_tf32<false><<<grid, 256>>>(f_all, W_gcn, nullptr, d_h, NNODE, DIM, DIM, 0, 0);
    }
    k_gcn_node<<<(NNODE * 32 + 255) / 256, 256>>>(src, b_gcn);

    // QKV + skip projections
    {
        dim3 gq((HC + 127) / 128, (NNODE + 127) / 128);
        gemm_tf32<false><<<gq, 256>>>(d_x, W_q, b_q, d_q, NNODE, HC, DIM, 1, 0);
        gemm_tf32<false><<<gq, 256>>>(d_x, W_k, b_k, d_k, NNODE, HC, DIM, 1, 0);
        gemm_tf32<false><<<gq, 256>>>(d_x, W_v, b_v, d_v, NNODE, HC, DIM, 1, 0);
        dim3 gs((DIM + 127) / 128, (NNODE + 127) / 128);
        gemm_tf32<false><<<gs, 256>>>(d_x, W_skip, b_skip, d_skip, NNODE, DIM, DIM, 1, 0);
    }

    // attention
    k_logits_csr<<<(NNODE * HEADS * 32 + 255) / 256, 256>>>(src);
    k_agg_csr<<<(NNODE * 32 + 255) / 256, 256>>>(src);

    // gate
    k_beta<<<(NNODE * 32 + 255) / 256, 256>>>(W_beta);

    // final: out[c, n] = sum_d W_cnn[c,d] * tf[n,d] + b_cnn[c]   (NT gemm, per-row bias)
    {
        dim3 grid((NNODE + 127) / 128, (DIM + 127) / 128);
        gemm_tf32<true><<<grid, 256>>>(W_cnn, d_x, b_cnn, out, DIM, NNODE, DIM, 2, 0);
    }
}

// round 4
// speedup vs baseline: 3.9162x; 1.7702x over previous
#include <cuda_runtime.h>
#include <cuda_fp16.h>
#include <math.h>

#define NNODE 20000
#define DIM 256
#define HEADS 4
#define NE 100000
#define HC 1024          // HEADS * C
#define NQKVS 3328       // 3*1024 + 256 packed q,k,v,skip

// ---------------- scratch (device globals; no allocation allowed) ----------
__device__ __align__(16) float g_dinv[NNODE];
__device__ __align__(16) __half g_fh[NNODE * DIM];        // f_all half
__device__ __align__(16) __half g_hh[NNODE * DIM];        // GCN h half
__device__ __align__(16) __half g_xh[NNODE * DIM];        // x half -> later tf half
__device__ __align__(16) __half g_qkvs[(size_t)NNODE * NQKVS]; // packed q|k|v|skip
__device__ __align__(16) __half g_wgcn[DIM * DIM];
__device__ __align__(16) __half g_wqkvs[DIM * NQKVS];
__device__ __align__(16) __half g_wcnn[DIM * DIM];
__device__ __align__(16) float  g_bqkvs[NQKVS];
__device__ __align__(16) float g_logits[NE * HEADS];
__device__ __align__(16) float g_denom[NNODE * HEADS];
__device__ __align__(16) float g_agg[NNODE * DIM];

// CSR by destination node
__device__ int g_cnt[NNODE];
__device__ int g_rowptr[NNODE + 1];
__device__ int g_fill[NNODE];
__device__ int g_eid[NE];

// ---------------- init / CSR build -----------------------------------------
__global__ void k_init() {
    int i = blockIdx.x * blockDim.x + threadIdx.x;
    if (i < NNODE) g_cnt[i] = 0;
}

__global__ void k_count(const int* __restrict__ dst) {
    int e = blockIdx.x * blockDim.x + threadIdx.x;
    if (e < NE) atomicAdd(&g_cnt[dst[e]], 1);
}

__global__ void k_scan() {
    __shared__ int sh[1024];
    __shared__ int soff;
    int tid = threadIdx.x;
    if (tid == 0) soff = 0;
    __syncthreads();
    for (int base = 0; base < NNODE; base += 1024) {
        int i = base + tid;
        int v = (i < NNODE) ? g_cnt[i] : 0;
        sh[tid] = v;
        __syncthreads();
        for (int d = 1; d < 1024; d <<= 1) {
            int t = (tid >= d) ? sh[tid - d] : 0;
            __syncthreads();
            sh[tid] += t;
            __syncthreads();
        }
        if (i < NNODE) {
            int excl = soff + sh[tid] - v;
            g_rowptr[i] = excl;
            g_fill[i]   = excl;
        }
        __syncthreads();
        if (tid == 1023) soff += sh[1023];
        __syncthreads();
    }
    if (tid == 0) g_rowptr[NNODE] = NE;
}

__global__ void k_dinv() {
    int i = blockIdx.x * blockDim.x + threadIdx.x;
    if (i < NNODE) {
        float d = (float)(g_rowptr[i + 1] - g_rowptr[i]) + 1.0f;
        g_dinv[i] = rsqrtf(d);
    }
}

__global__ void k_fill(const int* __restrict__ dst) {
    int e = blockIdx.x * blockDim.x + threadIdx.x;
    if (e < NE) {
        int pos = atomicAdd(&g_fill[dst[e]], 1);
        g_eid[pos] = e;
    }
}

// ---------------- pack: fp32 -> fp16 inputs/weights -------------------------
__global__ void k_pack(const float* __restrict__ f_all,
                       const float* __restrict__ W_gcn,
                       const float* __restrict__ W_q, const float* __restrict__ W_k,
                       const float* __restrict__ W_v, const float* __restrict__ W_skip,
                       const float* __restrict__ b_q, const float* __restrict__ b_k,
                       const float* __restrict__ b_v, const float* __restrict__ b_skip,
                       const float* __restrict__ W_cnn) {
    int i = blockIdx.x * blockDim.x + threadIdx.x;
    if (i < NNODE * DIM) g_fh[i] = __float2half_rn(f_all[i]);
    if (i < DIM * NQKVS) {
        int kk = i / NQKVS, j = i - kk * NQKVS;
        float v;
        if (j < 1024)      v = W_q[kk * 1024 + j];
        else if (j < 2048) v = W_k[kk * 1024 + j - 1024];
        else if (j < 3072) v = W_v[kk * 1024 + j - 2048];
        else               v = W_skip[kk * 256 + j - 3072];
        g_wqkvs[i] = __float2half_rn(v);
    }
    if (i < DIM * DIM) {
        g_wgcn[i] = __float2half_rn(W_gcn[i]);
        g_wcnn[i] = __float2half_rn(W_cnn[i]);
    }
    if (i < NQKVS) {
        float b;
        if (i < 1024)      b = b_q[i];
        else if (i < 2048) b = b_k[i - 1024];
        else if (i < 3072) b = b_v[i - 2048];
        else               b = b_skip[i - 3072];
        g_bqkvs[i] = b;
    }
}

// ---------------- fp16 tensor-core GEMM ------------------------------------
// C[M,N] = A[M,K] @ op(B) + bias.  BTRANS=false: B [K,N]; true: B [N,K].
// bias_mode: 0 none, 1 per-col, 2 per-row.  Block 128x128, BK=32, 2-stage cp.async.
__device__ __forceinline__ unsigned sptr(const void* p) {
    return (unsigned)__cvta_generic_to_shared(p);
}

template <bool BTRANS, typename OutT>
__global__ __launch_bounds__(256) void hgemm(
    const __half* __restrict__ A, const __half* __restrict__ B,
    const float* __restrict__ bias, OutT* __restrict__ C,
    int M, int N, int K, int bias_mode)
{
    const int BM = 128, BN = 128, BK = 32;
    const int LDA = 40;                        // halves (80B rows)
    const int LDB = BTRANS ? 40 : 136;         // NT: [BN][BK]; NN: [BK][BN] (272B rows)
    const int ABYTES = BM * LDA * 2;           // 10240
    const int BBYTES = (BTRANS ? BN * 40 : BK * 136) * 2;
    __shared__ __align__(16) char smraw[2 * ABYTES + 2 * ((BTRANS ? 128 * 40 : 32 * 136) * 2)];

    auto Asm = [&](int st) { return (__half*)(smraw + st * ABYTES); };
    auto Bsm = [&](int st) { return (__half*)(smraw + 2 * ABYTES + st * BBYTES); };

    int tid = threadIdx.x;
    int wid = tid >> 5, lane = tid & 31;
    int wm = (wid >> 2) * 64, wn = (wid & 3) * 32;
    int brow = blockIdx.y * BM;
    int bcol = blockIdx.x * BN;

    auto loadStage = [&](int st, int k0) {
        __half* as = Asm(st);
        __half* bs = Bsm(st);
#pragma unroll
        for (int i = 0; i < 2; i++) {
            int id = tid + 256 * i;
            // A: 128 rows x 4 chunks(16B)
            int r = id >> 2, c = id & 3;
            int gr = brow + r;
            const __half* gp = A + (size_t)(gr < M ? gr : M - 1) * K + k0 + c * 8;
            unsigned sa = sptr(as + r * LDA + c * 8);
            int sz = (gr < M) ? 16 : 0;
            asm volatile("cp.async.cg.shared.global [%0], [%1], 16, %2;\n"
                         :: "r"(sa), "l"(gp), "r"(sz));
            // B
            if (!BTRANS) {
                int kr = id >> 4, cc = id & 15;   // 32 rows x 16 chunks
                int gc = bcol + cc * 8;
                const __half* bp = B + (size_t)(k0 + kr) * N + (gc < N ? gc : 0);
                unsigned sb = sptr(bs + kr * 136 + cc * 8);
                int bsz = (gc < N) ? 16 : 0;
                asm volatile("cp.async.cg.shared.global [%0], [%1], 16, %2;\n"
                             :: "r"(sb), "l"(bp), "r"(bsz));
            } else {
                int nr = id >> 2, cc = id & 3;    // 128 rows x 4 chunks
                int gn = bcol + nr;
                const __half* bp = B + (size_t)(gn < N ? gn : N - 1) * K + k0 + cc * 8;
                unsigned sb = sptr(bs + nr * 40 + cc * 8);
                int bsz = (gn < N) ? 16 : 0;
                asm volatile("cp.async.cg.shared.global [%0], [%1], 16, %2;\n"
                             :: "r"(sb), "l"(bp), "r"(bsz));
            }
        }
        asm volatile("cp.async.commit_group;\n");
    };

    float acc[4][4][4];
#pragma unroll
    for (int a = 0; a < 4; a++)
#pragma unroll
        for (int b = 0; b < 4; b++)
#pragma unroll
            for (int c = 0; c < 4; c++) acc[a][b][c] = 0.0f;

    int nk = K / BK;
    loadStage(0, 0);

    for (int kt = 0; kt < nk; kt++) {
        if (kt + 1 < nk) loadStage((kt + 1) & 1, (kt + 1) * BK);
        else asm volatile("cp.async.commit_group;\n");
        asm volatile("cp.async.wait_group 1;\n");
        __syncthreads();

        int st = kt & 1;
        __half* as = Asm(st);
        __half* bs = Bsm(st);
#pragma unroll
        for (int ks = 0; ks < 2; ks++) {
            int k0s = ks * 16;
            unsigned af[4][4];
#pragma unroll
            for (int mt = 0; mt < 4; mt++) {
                unsigned addr = sptr(as + (wm + mt * 16 + (lane & 15)) * LDA
                                        + k0s + (lane >> 4) * 8);
                asm volatile("ldmatrix.sync.aligned.m8n8.x4.shared.b16 {%0,%1,%2,%3}, [%4];"
                             : "=r"(af[mt][0]), "=r"(af[mt][1]), "=r"(af[mt][2]), "=r"(af[mt][3])
                             : "r"(addr));
            }
            unsigned bf[4][2];
#pragma unroll
            for (int p = 0; p < 2; p++) {
                unsigned r0, r1, r2, r3;
                if (!BTRANS) {
                    int krow = k0s + (lane & 7) + ((lane >> 3) & 1) * 8;
                    int ncol = wn + p * 16 + (lane >> 4) * 8;
                    unsigned addr = sptr(bs + krow * 136 + ncol);
                    asm volatile("ldmatrix.sync.aligned.m8n8.x4.trans.shared.b16 {%0,%1,%2,%3}, [%4];"
                                 : "=r"(r0), "=r"(r1), "=r"(r2), "=r"(r3) : "r"(addr));
                } else {
                    int nrow = wn + p * 16 + (lane & 7) + (lane >> 4) * 8;
                    int kcol = k0s + ((lane >> 3) & 1) * 8;
                    unsigned addr = sptr(bs + nrow * 40 + kcol);
                    asm volatile("ldmatrix.sync.aligned.m8n8.x4.shared.b16 {%0,%1,%2,%3}, [%4];"
                                 : "=r"(r0), "=r"(r1), "=r"(r2), "=r"(r3) : "r"(addr));
                }
                bf[2 * p][0] = r0; bf[2 * p][1] = r1;
                bf[2 * p + 1][0] = r2; bf[2 * p + 1][1] = r3;
            }
#pragma unroll
            for (int mt = 0; mt < 4; mt++)
#pragma unroll
                for (int nt = 0; nt < 4; nt++)
                    asm volatile(
                        "mma.sync.aligned.m16n8k16.row.col.f32.f16.f16.f32 "
                        "{%0,%1,%2,%3}, {%4,%5,%6,%7}, {%8,%9}, {%0,%1,%2,%3};"
                        : "+f"(acc[mt][nt][0]), "+f"(acc[mt][nt][1]),
                          "+f"(acc[mt][nt][2]), "+f"(acc[mt][nt][3])
                        : "r"(af[mt][0]), "r"(af[mt][1]), "r"(af[mt][2]), "r"(af[mt][3]),
                          "r"(bf[nt][0]), "r"(bf[nt][1]));
        }
        __syncthreads();
    }

    int g = lane >> 2, t = lane & 3;
#pragma unroll
    for (int mt = 0; mt < 4; mt++) {
#pragma unroll
        for (int nt = 0; nt < 4; nt++) {
            int col = bcol + wn + nt * 8 + 2 * t;
            if (col >= N) continue;
            float bc0 = 0.f, bc1 = 0.f;
            if (bias_mode == 1) { bc0 = bias[col]; bc1 = bias[col + 1]; }
#pragma unroll
            for (int hf = 0; hf < 2; hf++) {
                int r = brow + wm + mt * 16 + g + 8 * hf;
                if (r >= M) continue;
                float v0 = acc[mt][nt][2 * hf + 0];
                float v1 = acc[mt][nt][2 * hf + 1];
                if (bias_mode == 1) { v0 += bc0; v1 += bc1; }
                else if (bias_mode == 2) { float br = bias[r]; v0 += br; v1 += br; }
                if (sizeof(OutT) == 2) {
                    __half2 hv = __floats2half2_rn(v0, v1);
                    *(__half2*)((__half*)C + (size_t)r * N + col) = hv;
                } else {
                    *(float2*)((float*)C + (size_t)r * N + col) = make_float2(v0, v1);
                }
            }
        }
    }
}

// ---------------- half helpers ----------------------------------------------
__device__ __forceinline__ void h8_to_f(const uint4& u, float* f) {
    const __half2* h = (const __half2*)&u;
#pragma unroll
    for (int i = 0; i < 4; i++) {
        float2 x = __half22float2(h[i]);
        f[2 * i] = x.x; f[2 * i + 1] = x.y;
    }
}

// ---------------- GCN aggregation: warp per destination node ----------------
__global__ void k_gcn_node(const int* __restrict__ src, const float* __restrict__ b_gcn) {
    int wid  = (blockIdx.x * blockDim.x + threadIdx.x) >> 5;
    int lane = threadIdx.x & 31;
    if (wid >= NNODE) return;
    int start = g_rowptr[wid], end = g_rowptr[wid + 1];
    float dn = g_dinv[wid];
    float acc[8];
#pragma unroll
    for (int i = 0; i < 8; i++) acc[i] = 0.0f;
    const uint4* hbase = (const uint4*)g_hh;
    for (int idx = start; idx < end; idx++) {
        int s = src[g_eid[idx]];
        float w = g_dinv[s] * dn;
        uint4 u = hbase[(size_t)s * (DIM / 8) + lane];
        float hv[8]; h8_to_f(u, hv);
#pragma unroll
        for (int i = 0; i < 8; i++) acc[i] = fmaf(w, hv[i], acc[i]);
    }
    float ws = dn * dn;
    uint4 u = hbase[(size_t)wid * (DIM / 8) + lane];
    float hv[8]; h8_to_f(u, hv);
    int c = lane * 8;
    __half2 out[4];
#pragma unroll
    for (int i = 0; i < 4; i++) {
        float v0 = fmaxf(fmaf(ws, hv[2 * i], acc[2 * i]) + b_gcn[c + 2 * i], 0.f);
        float v1 = fmaxf(fmaf(ws, hv[2 * i + 1], acc[2 * i + 1]) + b_gcn[c + 2 * i + 1], 0.f);
        out[i] = __floats2half2_rn(v0, v1);
    }
    *(uint4*)(g_xh + (size_t)wid * DIM + c) = *(uint4*)out;
}

// ---------------- attention: logits + softmax (warp per node-head) ----------
__global__ void k_logits_csr(const int* __restrict__ src) {
    int wid  = (blockIdx.x * blockDim.x + threadIdx.x) >> 5;
    int lane = threadIdx.x & 31;
    if (wid >= NNODE * HEADS) return;
    int n = wid >> 2, h = wid & 3;
    int start = g_rowptr[n], end = g_rowptr[n + 1];
    uint4 qu = *(const uint4*)(g_qkvs + (size_t)n * NQKVS + h * DIM + lane * 8);
    float qf[8]; h8_to_f(qu, qf);
    float maxl = -INFINITY;
    for (int idx = start; idx < end; idx++) {
        int e = g_eid[idx];
        int s = src[e];
        uint4 ku = *(const uint4*)(g_qkvs + (size_t)s * NQKVS + 1024 + h * DIM + lane * 8);
        float kf[8]; h8_to_f(ku, kf);
        float sum = 0.f;
#pragma unroll
        for (int i = 0; i < 8; i++) sum = fmaf(qf[i], kf[i], sum);
#pragma unroll
        for (int off = 16; off > 0; off >>= 1)
            sum += __shfl_xor_sync(0xFFFFFFFFu, sum, off);
        float l = sum * (1.0f / 16.0f);
        if (lane == ((idx - start) & 31)) g_logits[e * HEADS + h] = l;
        maxl = fmaxf(maxl, l);
    }
    float dsum = 0.0f;
    for (int idx = start + lane; idx < end; idx += 32) {
        int e = g_eid[idx];
        float tv = __expf(g_logits[e * HEADS + h] - maxl);
        g_logits[e * HEADS + h] = tv;
        dsum += tv;
    }
#pragma unroll
    for (int off = 16; off > 0; off >>= 1)
        dsum += __shfl_xor_sync(0xFFFFFFFFu, dsum, off);
    if (lane == 0) g_denom[n * HEADS + h] = dsum;
}

// ---------------- attention aggregation: warp per destination node ----------
__global__ void k_agg_csr(const int* __restrict__ src) {
    int wid  = (blockIdx.x * blockDim.x + threadIdx.x) >> 5;
    int lane = threadIdx.x & 31;
    if (wid >= NNODE) return;
    int start = g_rowptr[wid], end = g_rowptr[wid + 1];
    float4 dn = *(const float4*)&g_denom[wid * HEADS];
    float rd[HEADS] = {0.25f / fmaxf(dn.x, 1e-16f), 0.25f / fmaxf(dn.y, 1e-16f),
                       0.25f / fmaxf(dn.z, 1e-16f), 0.25f / fmaxf(dn.w, 1e-16f)};
    float acc[8];
#pragma unroll
    for (int i = 0; i < 8; i++) acc[i] = 0.0f;
    for (int idx = start; idx < end; idx++) {
        int e = g_eid[idx];
        int s = src[e];
        float4 t4 = *(const float4*)&g_logits[e * HEADS];
        float a[HEADS] = {t4.x * rd[0], t4.y * rd[1], t4.z * rd[2], t4.w * rd[3]};
        const __half* vp = g_qkvs + (size_t)s * NQKVS + 2048 + lane * 8;
#pragma unroll
        for (int h = 0; h < HEADS; h++) {
            uint4 vu = *(const uint4*)(vp + h * DIM);
            float vf[8]; h8_to_f(vu, vf);
#pragma unroll
            for (int i = 0; i < 8; i++) acc[i] = fmaf(a[h], vf[i], acc[i]);
        }
    }
    float* o = &g_agg[(size_t)wid * DIM + lane * 8];
    *(float4*)o = make_float4(acc[0], acc[1], acc[2], acc[3]);
    *(float4*)(o + 4) = make_float4(acc[4], acc[5], acc[6], acc[7]);
}

// ---------------- beta gate -> tf half (writes into g_xh) -------------------
__global__ void k_beta(const float* __restrict__ W_beta) {
    int wid  = (blockIdx.x * blockDim.x + threadIdx.x) >> 5;
    int lane = threadIdx.x & 31;
    if (wid >= NNODE) return;
    float o[8], r[8];
    float s = 0.0f;
#pragma unroll
    for (int i = 0; i < 8; i++) {
        int c = lane + i * 32;
        o[i] = g_agg[(size_t)wid * DIM + c];
        r[i] = __half2float(g_qkvs[(size_t)wid * NQKVS + 3072 + c]);
        s += o[i] * W_beta[c] + r[i] * W_beta[DIM + c] + (o[i] - r[i]) * W_beta[2 * DIM + c];
    }
#pragma unroll
    for (int off = 16; off > 0; off >>= 1)
        s += __shfl_xor_sync(0xFFFFFFFFu, s, off);
    float beta = 1.0f / (1.0f + __expf(-s));
#pragma unroll
    for (int i = 0; i < 8; i++) {
        int c = lane + i * 32;
        float tf = beta * r[i] + (1.0f - beta) * o[i];
        g_xh[(size_t)wid * DIM + c] = __float2half_rn(fmaxf(tf, 0.0f));
    }
}

// ---------------- launch ----------------------------------------------------
extern "C" void kernel_launch(void* const* d_in, const int* in_sizes, int n_in,
                              void* d_out, int out_size) {
    const float* f_all  = (const float*)d_in[0];
    const int*   eidx   = (const int*)d_in[1];
    const float* W_gcn  = (const float*)d_in[2];
    const float* b_gcn  = (const float*)d_in[3];
    const float* W_q    = (const float*)d_in[4];
    const float* b_q    = (const float*)d_in[5];
    const float* W_k    = (const float*)d_in[6];
    const float* b_k    = (const float*)d_in[7];
    const float* W_v    = (const float*)d_in[8];
    const float* b_v    = (const float*)d_in[9];
    const float* W_skip = (const float*)d_in[10];
    const float* b_skip = (const float*)d_in[11];
    const float* W_beta = (const float*)d_in[12];
    const float* W_cnn  = (const float*)d_in[13];
    const float* b_cnn  = (const float*)d_in[14];
    float* out = (float*)d_out;

    const int* src = eidx;
    const int* dst = eidx + NE;

    __half* d_fh = nullptr;  cudaGetSymbolAddress((void**)&d_fh,  g_fh);
    __half* d_hh = nullptr;  cudaGetSymbolAddress((void**)&d_hh,  g_hh);
    __half* d_xh = nullptr;  cudaGetSymbolAddress((void**)&d_xh,  g_xh);
    __half* d_qkvs = nullptr; cudaGetSymbolAddress((void**)&d_qkvs, g_qkvs);
    __half* d_wgcn = nullptr; cudaGetSymbolAddress((void**)&d_wgcn, g_wgcn);
    __half* d_wqkvs = nullptr; cudaGetSymbolAddress((void**)&d_wqkvs, g_wqkvs);
    __half* d_wcnn = nullptr; cudaGetSymbolAddress((void**)&d_wcnn, g_wcnn);
    float*  d_bqkvs = nullptr; cudaGetSymbolAddress((void**)&d_bqkvs, g_bqkvs);

    // CSR build + pack
    k_init<<<(NNODE + 255) / 256, 256>>>();
    k_count<<<(NE + 255) / 256, 256>>>(dst);
    k_scan<<<1, 1024>>>();
    k_dinv<<<(NNODE + 255) / 256, 256>>>();
    k_fill<<<(NE + 255) / 256, 256>>>(dst);
    k_pack<<<(NNODE * DIM + 255) / 256, 256>>>(f_all, W_gcn, W_q, W_k, W_v, W_skip,
                                               b_q, b_k, b_v, b_skip, W_cnn);

    // GCN: h = f_all @ W_gcn  (half out), then per-node aggregation
    {
        dim3 grid(DIM / 128, (NNODE + 127) / 128);
        hgemm<false, __half><<<grid, 256>>>(d_fh, d_wgcn, nullptr, d_hh, NNODE, DIM, DIM, 0);
    }
    k_gcn_node<<<(NNODE * 32 + 255) / 256, 256>>>(src, b_gcn);

    // fused Q|K|V|skip projection: [20000,256] @ [256,3328]
    {
        dim3 grid(NQKVS / 128, (NNODE + 127) / 128);
        hgemm<false, __half><<<grid, 256>>>(d_xh, d_wqkvs, d_bqkvs, d_qkvs, NNODE, NQKVS, DIM, 1);
    }

    // attention
    k_logits_csr<<<(NNODE * HEADS * 32 + 255) / 256, 256>>>(src);
    k_agg_csr<<<(NNODE * 32 + 255) / 256, 256>>>(src);

    // gate -> tf (half, into g_xh)
    k_beta<<<(NNODE * 32 + 255) / 256, 256>>>(W_beta);

    // final: out[c,n] = W_cnn[c,:] . tf[n,:] + b_cnn[c]   (NT, fp32 out, per-row bias)
    {
        dim3 grid((NNODE + 127) / 128, DIM / 128);
        hgemm<true, float><<<grid, 256>>>(d_wcnn, d_xh, b_cnn, out, DIM, NNODE, DIM, 2);
    }
}